// round 2
// baseline (speedup 1.0000x reference)
#include <cuda_runtime.h>
#include <cuda_bf16.h>
#include <cstdint>

// Problem shape (fixed by the reference):
//   x        [B=4, S=4096, D=2048]  fp32  -> M = 16384, K1 = 2048
//   w_up     [DI=8192, D=2048]      fp32  (K-major for GEMM1)
//   b_up     [8192]                 fp32
//   w_down_q [D=2048, DI=8192]      int32 (int8 values; K-major for GEMM2)
//   w_down_scale [2048]             fp32
//   b_down   [2048]                 fp32
//   out      [16384, 2048]          fp32
//
// GEMM1: h[m,f] = gelu( sum_k x[m,k] * w_up[f,k] + b_up[f] )        (M x 8192, K=2048)
// GEMM2: out[m,o] = (sum_f h[m,f] * w_down_q[o,f]) * scale[o] + b_down[o]  (M x 2048, K=8192)

#define M_TOK   16384
#define D_IN    2048
#define D_HID   8192

#define BM 128
#define BN 128
#define BK 16
#define TM 8
#define TN 8
#define NTHREADS 256

// 512 MB scratch for the intermediate activation h (fp32 for accuracy).
__device__ float g_hidden[(size_t)M_TOK * D_HID];

__device__ __forceinline__ float gelu_exact(float v) {
    return 0.5f * v * (1.0f + erff(v * 0.70710678118654752f));
}

// ---------------------------------------------------------------------------
// Kernel 1: GEMM (A[M,K] @ B[N,K]^T) + bias + exact GELU -> g_hidden
// ---------------------------------------------------------------------------
__global__ __launch_bounds__(NTHREADS, 2)
void ffn_gemm1_gelu(const float* __restrict__ A,   // x, [M, 2048]
                    const float* __restrict__ B,   // w_up, [8192, 2048]
                    const float* __restrict__ bias // b_up, [8192]
) {
    const int K = D_IN;
    const int N = D_HID;

    __shared__ float As[BK][BM + 4];
    __shared__ float Bs[BK][BN + 4];

    const int tid = threadIdx.x;
    const int tx  = tid % 16;         // 0..15 -> N direction
    const int ty  = tid / 16;         // 0..15 -> M direction

    const int rowBase = blockIdx.y * BM;   // M offset
    const int colBase = blockIdx.x * BN;   // N offset

    // Tile-load mapping: 128 rows x 16 k = 512 float4; 256 threads x 2 each.
    const int ldRow = tid >> 2;            // 0..63
    const int ldK4  = (tid & 3) * 4;       // 0,4,8,12

    float acc[TM][TN];
    #pragma unroll
    for (int i = 0; i < TM; i++)
        #pragma unroll
        for (int j = 0; j < TN; j++)
            acc[i][j] = 0.0f;

    const float* Aptr = A + (size_t)(rowBase) * K;
    const float* Bptr = B + (size_t)(colBase) * K;

    for (int k0 = 0; k0 < K; k0 += BK) {
        // Load A tile (two 64-row halves), store transposed As[k][m]
        #pragma unroll
        for (int h = 0; h < 2; h++) {
            int r = ldRow + h * 64;
            float4 v = *(const float4*)(Aptr + (size_t)r * K + k0 + ldK4);
            As[ldK4 + 0][r] = v.x;
            As[ldK4 + 1][r] = v.y;
            As[ldK4 + 2][r] = v.z;
            As[ldK4 + 3][r] = v.w;
        }
        // Load B tile, store transposed Bs[k][n]
        #pragma unroll
        for (int h = 0; h < 2; h++) {
            int r = ldRow + h * 64;
            float4 v = *(const float4*)(Bptr + (size_t)r * K + k0 + ldK4);
            Bs[ldK4 + 0][r] = v.x;
            Bs[ldK4 + 1][r] = v.y;
            Bs[ldK4 + 2][r] = v.z;
            Bs[ldK4 + 3][r] = v.w;
        }
        __syncthreads();

        #pragma unroll
        for (int kk = 0; kk < BK; kk++) {
            float ar[TM], br[TN];
            float4 a0 = *(const float4*)&As[kk][ty * TM];
            float4 a1 = *(const float4*)&As[kk][ty * TM + 4];
            ar[0] = a0.x; ar[1] = a0.y; ar[2] = a0.z; ar[3] = a0.w;
            ar[4] = a1.x; ar[5] = a1.y; ar[6] = a1.z; ar[7] = a1.w;
            float4 b0 = *(const float4*)&Bs[kk][tx * TN];
            float4 b1 = *(const float4*)&Bs[kk][tx * TN + 4];
            br[0] = b0.x; br[1] = b0.y; br[2] = b0.z; br[3] = b0.w;
            br[4] = b1.x; br[5] = b1.y; br[6] = b1.z; br[7] = b1.w;
            #pragma unroll
            for (int i = 0; i < TM; i++)
                #pragma unroll
                for (int j = 0; j < TN; j++)
                    acc[i][j] = fmaf(ar[i], br[j], acc[i][j]);
        }
        __syncthreads();
    }

    // Epilogue: bias + exact GELU, vectorized store to g_hidden
    const int nBase = colBase + tx * TN;
    float bb[TN];
    #pragma unroll
    for (int j = 0; j < TN; j++) bb[j] = bias[nBase + j];

    #pragma unroll
    for (int i = 0; i < TM; i++) {
        int m = rowBase + ty * TM + i;
        float out[TN];
        #pragma unroll
        for (int j = 0; j < TN; j++)
            out[j] = gelu_exact(acc[i][j] + bb[j]);
        float* dst = g_hidden + (size_t)m * N + nBase;
        *(float4*)(dst)     = make_float4(out[0], out[1], out[2], out[3]);
        *(float4*)(dst + 4) = make_float4(out[4], out[5], out[6], out[7]);
    }
}

// ---------------------------------------------------------------------------
// Kernel 2: GEMM (h[M,K2] @ Wq[N2,K2]^T) * scale + bias -> out
// ---------------------------------------------------------------------------
__global__ __launch_bounds__(NTHREADS, 2)
void ffn_gemm2_q8(const int*   __restrict__ Bq,    // w_down_q, [2048, 8192] int32
                  const float* __restrict__ scale, // [2048]
                  const float* __restrict__ bias,  // [2048]
                  float*       __restrict__ Out    // [16384, 2048]
) {
    const int K = D_HID;
    const int N = D_IN;

    __shared__ float As[BK][BM + 4];
    __shared__ float Bs[BK][BN + 4];

    const int tid = threadIdx.x;
    const int tx  = tid % 16;
    const int ty  = tid / 16;

    const int rowBase = blockIdx.y * BM;
    const int colBase = blockIdx.x * BN;

    const int ldRow = tid >> 2;
    const int ldK4  = (tid & 3) * 4;

    float acc[TM][TN];
    #pragma unroll
    for (int i = 0; i < TM; i++)
        #pragma unroll
        for (int j = 0; j < TN; j++)
            acc[i][j] = 0.0f;

    const float* Aptr = g_hidden + (size_t)(rowBase) * K;
    const int*   Bptr = Bq + (size_t)(colBase) * K;

    for (int k0 = 0; k0 < K; k0 += BK) {
        #pragma unroll
        for (int h = 0; h < 2; h++) {
            int r = ldRow + h * 64;
            float4 v = *(const float4*)(Aptr + (size_t)r * K + k0 + ldK4);
            As[ldK4 + 0][r] = v.x;
            As[ldK4 + 1][r] = v.y;
            As[ldK4 + 2][r] = v.z;
            As[ldK4 + 3][r] = v.w;
        }
        #pragma unroll
        for (int h = 0; h < 2; h++) {
            int r = ldRow + h * 64;
            int4 v = *(const int4*)(Bptr + (size_t)r * K + k0 + ldK4);
            Bs[ldK4 + 0][r] = (float)v.x;
            Bs[ldK4 + 1][r] = (float)v.y;
            Bs[ldK4 + 2][r] = (float)v.z;
            Bs[ldK4 + 3][r] = (float)v.w;
        }
        __syncthreads();

        #pragma unroll
        for (int kk = 0; kk < BK; kk++) {
            float ar[TM], br[TN];
            float4 a0 = *(const float4*)&As[kk][ty * TM];
            float4 a1 = *(const float4*)&As[kk][ty * TM + 4];
            ar[0] = a0.x; ar[1] = a0.y; ar[2] = a0.z; ar[3] = a0.w;
            ar[4] = a1.x; ar[5] = a1.y; ar[6] = a1.z; ar[7] = a1.w;
            float4 b0 = *(const float4*)&Bs[kk][tx * TN];
            float4 b1 = *(const float4*)&Bs[kk][tx * TN + 4];
            br[0] = b0.x; br[1] = b0.y; br[2] = b0.z; br[3] = b0.w;
            br[4] = b1.x; br[5] = b1.y; br[6] = b1.z; br[7] = b1.w;
            #pragma unroll
            for (int i = 0; i < TM; i++)
                #pragma unroll
                for (int j = 0; j < TN; j++)
                    acc[i][j] = fmaf(ar[i], br[j], acc[i][j]);
        }
        __syncthreads();
    }

    const int nBase = colBase + tx * TN;
    float ss[TN], bb[TN];
    #pragma unroll
    for (int j = 0; j < TN; j++) { ss[j] = scale[nBase + j]; bb[j] = bias[nBase + j]; }

    #pragma unroll
    for (int i = 0; i < TM; i++) {
        int m = rowBase + ty * TM + i;
        float out[TN];
        #pragma unroll
        for (int j = 0; j < TN; j++)
            out[j] = fmaf(acc[i][j], ss[j], bb[j]);
        float* dst = Out + (size_t)m * N + nBase;
        *(float4*)(dst)     = make_float4(out[0], out[1], out[2], out[3]);
        *(float4*)(dst + 4) = make_float4(out[4], out[5], out[6], out[7]);
    }
}

// ---------------------------------------------------------------------------
// Launch
// ---------------------------------------------------------------------------
extern "C" void kernel_launch(void* const* d_in, const int* in_sizes, int n_in,
                              void* d_out, int out_size) {
    const float* x        = (const float*)d_in[0];  // [16384, 2048]
    const float* w_up     = (const float*)d_in[1];  // [8192, 2048]
    const float* b_up     = (const float*)d_in[2];  // [8192]
    const int*   w_down_q = (const int*)  d_in[3];  // [2048, 8192]
    const float* w_scale  = (const float*)d_in[4];  // [2048]
    const float* b_down   = (const float*)d_in[5];  // [2048]
    float*       out      = (float*)d_out;          // [16384, 2048]

    (void)in_sizes; (void)n_in; (void)out_size;

    dim3 block(NTHREADS);
    dim3 grid1(D_HID / BN, M_TOK / BM);   // 64 x 128
    dim3 grid2(D_IN / BN,  M_TOK / BM);   // 16 x 128

    ffn_gemm1_gelu<<<grid1, block>>>(x, w_up, b_up);
    ffn_gemm2_q8<<<grid2, block>>>(w_down_q, w_scale, b_down, out);
}

// round 6
// speedup vs baseline: 2.9317x; 2.9317x over previous
#include <cuda_runtime.h>
#include <cuda_bf16.h>
#include <cstdint>

// FFN: out = (gelu(x @ w_up^T + b_up) @ w_down_q^T) * scale + b_down
// tcgen05 unavailable (harness compiles virtual arch compute_103, no 'a').
// Use mma.sync.m16n8k16 bf16 (HMMA) with hi/lo bf16 split for fp32 accuracy.

#define M_TOK 16384
#define D_IN  2048
#define D_HID 8192

#define BM 128
#define BN 256
#define BK 32
#define NTHREADS 256

// ---------------- device scratch ----------------
__device__ __nv_bfloat16 g_x_hi[(size_t)M_TOK * D_IN];
__device__ __nv_bfloat16 g_x_lo[(size_t)M_TOK * D_IN];
__device__ __nv_bfloat16 g_wu_hi[(size_t)D_HID * D_IN];
__device__ __nv_bfloat16 g_wu_lo[(size_t)D_HID * D_IN];
__device__ __nv_bfloat16 g_wd_bf[(size_t)D_IN * D_HID];
__device__ __nv_bfloat16 g_h_hi[(size_t)M_TOK * D_HID];
__device__ __nv_bfloat16 g_h_lo[(size_t)M_TOK * D_HID];

// ---------------- helpers ----------------
__device__ __forceinline__ uint32_t smem_u32(const void* p) {
    uint32_t a;
    asm("{ .reg .u64 t; cvta.to.shared.u64 t, %1; cvt.u32.u64 %0, t; }" : "=r"(a) : "l"(p));
    return a;
}
__device__ __forceinline__ void cp16(uint32_t dst, const void* src) {
    asm volatile("cp.async.cg.shared.global [%0], [%1], 16;" :: "r"(dst), "l"(src));
}
__device__ __forceinline__ void cp_commit() { asm volatile("cp.async.commit_group;"); }
#define CP_WAIT(N) asm volatile("cp.async.wait_group %0;" :: "n"(N))

__device__ __forceinline__ void ldm_x4(uint32_t* r, uint32_t addr) {
    asm volatile("ldmatrix.sync.aligned.m8n8.x4.shared.b16 {%0,%1,%2,%3}, [%4];"
                 : "=r"(r[0]), "=r"(r[1]), "=r"(r[2]), "=r"(r[3]) : "r"(addr));
}
__device__ __forceinline__ void mma_bf16(float* c, const uint32_t* a, uint32_t b0, uint32_t b1) {
    asm volatile(
        "mma.sync.aligned.m16n8k16.row.col.f32.bf16.bf16.f32 "
        "{%0,%1,%2,%3}, {%4,%5,%6,%7}, {%8,%9}, {%0,%1,%2,%3};"
        : "+f"(c[0]), "+f"(c[1]), "+f"(c[2]), "+f"(c[3])
        : "r"(a[0]), "r"(a[1]), "r"(a[2]), "r"(a[3]), "r"(b0), "r"(b1));
}

// Tile in SMEM: ROWS rows x 32 bf16 (64B rows), swizzle: unit' = u ^ ((r>>1)&3)
template <int ROWS>
__device__ __forceinline__ void load_tile(uint32_t smem_dst,
                                          const __nv_bfloat16* __restrict__ g,
                                          int ldg, int row0, int k0) {
    const int t = threadIdx.x;
    const int r = t >> 2;
    const int u = t & 3;
#pragma unroll
    for (int p = 0; p < ROWS / 64; p++) {
        const int rr = r + p * 64;
        const __nv_bfloat16* src = g + (size_t)(row0 + rr) * ldg + k0 + u * 8;
        const uint32_t dst = smem_dst + rr * 64 + ((u ^ ((rr >> 1) & 3)) * 16);
        cp16(dst, src);
    }
}

// ldmatrix x4 address for a 16x16 bf16 fragment at tile-row R0, k16-step s.
__device__ __forceinline__ uint32_t frag_addr(uint32_t base, int R0, int s, int lane) {
    const int r = R0 + (lane & 15);
    const int u = 2 * s + (lane >> 4);
    return base + r * 64 + ((u ^ ((r >> 1) & 3)) * 16);
}

__device__ __forceinline__ float gelu_exact(float v) {
    return 0.5f * v * (1.0f + erff(v * 0.70710678118654752f));
}

// ===========================================================================
// GEMM1: h = gelu(x @ w_up^T + b_up); acc = xh*wh + al*wh + xh*wl
// tiles: Ah@0(8K) Al@8K Bh@16K(16K) Bl@32K(16K); stage=48K, 3 stages
// ===========================================================================
#define G1_NS 3
#define G1_STAGE 49152
#define G1_SMEM (G1_NS * G1_STAGE + 1024)

__global__ __launch_bounds__(NTHREADS, 1)
void ffn_g1_mma(const float* __restrict__ bias) {
    extern __shared__ char smem[];
    const uint32_t sb = smem_u32(smem);
    const int tid = threadIdx.x, lane = tid & 31, w = tid >> 5;
    const int wm = w & 1, wn = w >> 1;
    const int rowBase = blockIdx.y * BM;
    const int colBase = blockIdx.x * BN;

    float* bs = (float*)(smem + G1_NS * G1_STAGE);
    bs[tid] = bias[colBase + tid];

    float acc[4][8][4];
#pragma unroll
    for (int a = 0; a < 4; a++)
#pragma unroll
        for (int b = 0; b < 8; b++)
#pragma unroll
            for (int c = 0; c < 4; c++) acc[a][b][c] = 0.0f;

    const int nCh = D_IN / BK;  // 64

    for (int s = 0; s < G1_NS - 1; s++) {
        const uint32_t st = sb + s * G1_STAGE;
        load_tile<128>(st,         g_x_hi,  D_IN, rowBase, s * BK);
        load_tile<128>(st + 8192,  g_x_lo,  D_IN, rowBase, s * BK);
        load_tile<256>(st + 16384, g_wu_hi, D_IN, colBase, s * BK);
        load_tile<256>(st + 32768, g_wu_lo, D_IN, colBase, s * BK);
        cp_commit();
    }

    for (int i = 0; i < nCh; i++) {
        CP_WAIT(G1_NS - 2);
        __syncthreads();
        const uint32_t st = sb + (i % G1_NS) * G1_STAGE;
        if (i + G1_NS - 1 < nCh) {
            const uint32_t st2 = sb + ((i + G1_NS - 1) % G1_NS) * G1_STAGE;
            const int k0 = (i + G1_NS - 1) * BK;
            load_tile<128>(st2,         g_x_hi,  D_IN, rowBase, k0);
            load_tile<128>(st2 + 8192,  g_x_lo,  D_IN, rowBase, k0);
            load_tile<256>(st2 + 16384, g_wu_hi, D_IN, colBase, k0);
            load_tile<256>(st2 + 32768, g_wu_lo, D_IN, colBase, k0);
        }
        cp_commit();

#pragma unroll
        for (int s = 0; s < 2; s++) {
            uint32_t ah[4][4], al[4][4];
#pragma unroll
            for (int mt = 0; mt < 4; mt++)
                ldm_x4(ah[mt], frag_addr(st, wm * 64 + mt * 16, s, lane));
#pragma unroll
            for (int mt = 0; mt < 4; mt++)
                ldm_x4(al[mt], frag_addr(st + 8192, wm * 64 + mt * 16, s, lane));
#pragma unroll
            for (int g = 0; g < 4; g++) {
                uint32_t b[4];
                ldm_x4(b, frag_addr(st + 16384, wn * 64 + g * 16, s, lane));
#pragma unroll
                for (int mt = 0; mt < 4; mt++) {
                    mma_bf16(acc[mt][2 * g],     ah[mt], b[0], b[2]);
                    mma_bf16(acc[mt][2 * g + 1], ah[mt], b[1], b[3]);
                }
#pragma unroll
                for (int mt = 0; mt < 4; mt++) {
                    mma_bf16(acc[mt][2 * g],     al[mt], b[0], b[2]);
                    mma_bf16(acc[mt][2 * g + 1], al[mt], b[1], b[3]);
                }
            }
#pragma unroll
            for (int g = 0; g < 4; g++) {
                uint32_t b[4];
                ldm_x4(b, frag_addr(st + 32768, wn * 64 + g * 16, s, lane));
#pragma unroll
                for (int mt = 0; mt < 4; mt++) {
                    mma_bf16(acc[mt][2 * g],     ah[mt], b[0], b[2]);
                    mma_bf16(acc[mt][2 * g + 1], ah[mt], b[1], b[3]);
                }
            }
        }
    }

    // epilogue: bias + gelu, split to hi/lo bf16
    const int mrow0 = rowBase + wm * 64 + (lane >> 2);
#pragma unroll
    for (int mt = 0; mt < 4; mt++) {
#pragma unroll
        for (int j = 0; j < 8; j++) {
            const int nl = wn * 64 + j * 8 + (lane & 3) * 2;
            const float b0 = bs[nl], b1 = bs[nl + 1];
            const float* c = acc[mt][j];
#pragma unroll
            for (int hrow = 0; hrow < 2; hrow++) {
                const float v0 = gelu_exact(c[2 * hrow]     + b0);
                const float v1 = gelu_exact(c[2 * hrow + 1] + b1);
                const __nv_bfloat16 h0 = __float2bfloat16(v0);
                const __nv_bfloat16 h1 = __float2bfloat16(v1);
                const __nv_bfloat16 l0 = __float2bfloat16(v0 - __bfloat162float(h0));
                const __nv_bfloat16 l1 = __float2bfloat16(v1 - __bfloat162float(h1));
                const uint32_t hp = (uint32_t)__bfloat16_as_ushort(h0) |
                                    ((uint32_t)__bfloat16_as_ushort(h1) << 16);
                const uint32_t lp = (uint32_t)__bfloat16_as_ushort(l0) |
                                    ((uint32_t)__bfloat16_as_ushort(l1) << 16);
                const size_t idx = (size_t)(mrow0 + mt * 16 + hrow * 8) * D_HID + colBase + nl;
                *(uint32_t*)(g_h_hi + idx) = hp;
                *(uint32_t*)(g_h_lo + idx) = lp;
            }
        }
    }
}

// ===========================================================================
// GEMM2: out = (h @ w_down^T) * scale + b_down; acc = hh*w + hl*w
// tiles: Ah@0(8K) Al@8K B@16K(16K); stage=32K, 4 stages
// ===========================================================================
#define G2_NS 4
#define G2_STAGE 32768
#define G2_SMEM (G2_NS * G2_STAGE + 2048)

__global__ __launch_bounds__(NTHREADS, 1)
void ffn_g2_mma(const float* __restrict__ scale, const float* __restrict__ bias,
                float* __restrict__ out) {
    extern __shared__ char smem[];
    const uint32_t sb = smem_u32(smem);
    const int tid = threadIdx.x, lane = tid & 31, w = tid >> 5;
    const int wm = w & 1, wn = w >> 1;
    const int rowBase = blockIdx.y * BM;
    const int colBase = blockIdx.x * BN;

    float* ss = (float*)(smem + G2_NS * G2_STAGE);
    float* bs = ss + 256;
    ss[tid] = scale[colBase + tid];
    bs[tid] = bias[colBase + tid];

    float acc[4][8][4];
#pragma unroll
    for (int a = 0; a < 4; a++)
#pragma unroll
        for (int b = 0; b < 8; b++)
#pragma unroll
            for (int c = 0; c < 4; c++) acc[a][b][c] = 0.0f;

    const int nCh = D_HID / BK;  // 256

    for (int s = 0; s < G2_NS - 1; s++) {
        const uint32_t st = sb + s * G2_STAGE;
        load_tile<128>(st,         g_h_hi,  D_HID, rowBase, s * BK);
        load_tile<128>(st + 8192,  g_h_lo,  D_HID, rowBase, s * BK);
        load_tile<256>(st + 16384, g_wd_bf, D_HID, colBase, s * BK);
        cp_commit();
    }

    for (int i = 0; i < nCh; i++) {
        CP_WAIT(G2_NS - 2);
        __syncthreads();
        const uint32_t st = sb + (i % G2_NS) * G2_STAGE;
        if (i + G2_NS - 1 < nCh) {
            const uint32_t st2 = sb + ((i + G2_NS - 1) % G2_NS) * G2_STAGE;
            const int k0 = (i + G2_NS - 1) * BK;
            load_tile<128>(st2,         g_h_hi,  D_HID, rowBase, k0);
            load_tile<128>(st2 + 8192,  g_h_lo,  D_HID, rowBase, k0);
            load_tile<256>(st2 + 16384, g_wd_bf, D_HID, colBase, k0);
        }
        cp_commit();

#pragma unroll
        for (int s = 0; s < 2; s++) {
            uint32_t ah[4][4], al[4][4];
#pragma unroll
            for (int mt = 0; mt < 4; mt++)
                ldm_x4(ah[mt], frag_addr(st, wm * 64 + mt * 16, s, lane));
#pragma unroll
            for (int mt = 0; mt < 4; mt++)
                ldm_x4(al[mt], frag_addr(st + 8192, wm * 64 + mt * 16, s, lane));
#pragma unroll
            for (int g = 0; g < 4; g++) {
                uint32_t b[4];
                ldm_x4(b, frag_addr(st + 16384, wn * 64 + g * 16, s, lane));
#pragma unroll
                for (int mt = 0; mt < 4; mt++) {
                    mma_bf16(acc[mt][2 * g],     ah[mt], b[0], b[2]);
                    mma_bf16(acc[mt][2 * g + 1], ah[mt], b[1], b[3]);
                }
#pragma unroll
                for (int mt = 0; mt < 4; mt++) {
                    mma_bf16(acc[mt][2 * g],     al[mt], b[0], b[2]);
                    mma_bf16(acc[mt][2 * g + 1], al[mt], b[1], b[3]);
                }
            }
        }
    }

    const int mrow0 = rowBase + wm * 64 + (lane >> 2);
#pragma unroll
    for (int mt = 0; mt < 4; mt++) {
#pragma unroll
        for (int j = 0; j < 8; j++) {
            const int nl = wn * 64 + j * 8 + (lane & 3) * 2;
            const float s0 = ss[nl], s1 = ss[nl + 1];
            const float b0 = bs[nl], b1 = bs[nl + 1];
            const float* c = acc[mt][j];
#pragma unroll
            for (int hrow = 0; hrow < 2; hrow++) {
                const float v0 = fmaf(c[2 * hrow],     s0, b0);
                const float v1 = fmaf(c[2 * hrow + 1], s1, b1);
                float* dst = out + (size_t)(mrow0 + mt * 16 + hrow * 8) * D_IN + colBase + nl;
                *(float2*)dst = make_float2(v0, v1);
            }
        }
    }
}

// ===========================================================================
// conversion kernels
// ===========================================================================
__global__ void split_f32(const float* __restrict__ in,
                          __nv_bfloat16* __restrict__ hi,
                          __nv_bfloat16* __restrict__ lo, int n4) {
    int i = blockIdx.x * blockDim.x + threadIdx.x;
    if (i >= n4) return;
    float4 v = ((const float4*)in)[i];
    float vv[4] = { v.x, v.y, v.z, v.w };
    uint32_t hp[2], lp[2];
#pragma unroll
    for (int q = 0; q < 2; q++) {
        __nv_bfloat16 h0 = __float2bfloat16(vv[2 * q]);
        __nv_bfloat16 h1 = __float2bfloat16(vv[2 * q + 1]);
        __nv_bfloat16 l0 = __float2bfloat16(vv[2 * q]     - __bfloat162float(h0));
        __nv_bfloat16 l1 = __float2bfloat16(vv[2 * q + 1] - __bfloat162float(h1));
        hp[q] = (uint32_t)__bfloat16_as_ushort(h0) | ((uint32_t)__bfloat16_as_ushort(h1) << 16);
        lp[q] = (uint32_t)__bfloat16_as_ushort(l0) | ((uint32_t)__bfloat16_as_ushort(l1) << 16);
    }
    ((uint2*)hi)[i] = make_uint2(hp[0], hp[1]);
    ((uint2*)lo)[i] = make_uint2(lp[0], lp[1]);
}

__global__ void cvt_i32_bf16(const int* __restrict__ q, __nv_bfloat16* __restrict__ o, int n4) {
    int i = blockIdx.x * blockDim.x + threadIdx.x;
    if (i >= n4) return;
    int4 v = ((const int4*)q)[i];
    uint32_t p0 = (uint32_t)__bfloat16_as_ushort(__float2bfloat16((float)v.x)) |
                  ((uint32_t)__bfloat16_as_ushort(__float2bfloat16((float)v.y)) << 16);
    uint32_t p1 = (uint32_t)__bfloat16_as_ushort(__float2bfloat16((float)v.z)) |
                  ((uint32_t)__bfloat16_as_ushort(__float2bfloat16((float)v.w)) << 16);
    ((uint2*)o)[i] = make_uint2(p0, p1);
}

// ===========================================================================
// launch
// ===========================================================================
extern "C" void kernel_launch(void* const* d_in, const int* in_sizes, int n_in,
                              void* d_out, int out_size) {
    const float* x        = (const float*)d_in[0];
    const float* w_up     = (const float*)d_in[1];
    const float* b_up     = (const float*)d_in[2];
    const int*   w_down_q = (const int*)  d_in[3];
    const float* w_scale  = (const float*)d_in[4];
    const float* b_down   = (const float*)d_in[5];
    float*       out      = (float*)d_out;
    (void)in_sizes; (void)n_in; (void)out_size;

    static bool attr_set = false;
    if (!attr_set) {
        cudaFuncSetAttribute(ffn_g1_mma, cudaFuncAttributeMaxDynamicSharedMemorySize, G1_SMEM);
        cudaFuncSetAttribute(ffn_g2_mma, cudaFuncAttributeMaxDynamicSharedMemorySize, G2_SMEM);
        attr_set = true;
    }

    __nv_bfloat16 *xh, *xl, *wh, *wl, *wd;
    cudaGetSymbolAddress((void**)&xh, g_x_hi);
    cudaGetSymbolAddress((void**)&xl, g_x_lo);
    cudaGetSymbolAddress((void**)&wh, g_wu_hi);
    cudaGetSymbolAddress((void**)&wl, g_wu_lo);
    cudaGetSymbolAddress((void**)&wd, g_wd_bf);

    {
        int n4 = (M_TOK * D_IN) / 4;
        split_f32<<<(n4 + 255) / 256, 256>>>(x, xh, xl, n4);
    }
    {
        int n4 = (D_HID * D_IN) / 4;
        split_f32<<<(n4 + 255) / 256, 256>>>(w_up, wh, wl, n4);
    }
    {
        int n4 = (D_IN * D_HID) / 4;
        cvt_i32_bf16<<<(n4 + 255) / 256, 256>>>(w_down_q, wd, n4);
    }

    dim3 block(NTHREADS);
    dim3 grid1(D_HID / BN, M_TOK / BM);  // 32 x 128
    dim3 grid2(D_IN / BN,  M_TOK / BM);  // 8 x 128

    ffn_g1_mma<<<grid1, block, G1_SMEM>>>(b_up);
    ffn_g2_mma<<<grid2, block, G2_SMEM>>>(w_scale, b_down, out);
}

// round 9
// speedup vs baseline: 2.9736x; 1.0143x over previous
#include <cuda_runtime.h>
#include <cuda_bf16.h>
#include <cstdint>

// FFN: out = (gelu(x @ w_up^T + b_up) @ w_down_q^T) * scale + b_down
// mma.sync m16n8k16 bf16 with hi/lo split (tcgen05 unavailable at compute_103).

#define M_TOK 16384
#define D_IN  2048
#define D_HID 8192

#define BM 128
#define BN 256
#define NTHREADS 256

// ---------------- device scratch ----------------
__device__ __nv_bfloat16 g_x_hi[(size_t)M_TOK * D_IN];
__device__ __nv_bfloat16 g_x_lo[(size_t)M_TOK * D_IN];
__device__ __nv_bfloat16 g_wu_hi[(size_t)D_HID * D_IN];
__device__ __nv_bfloat16 g_wu_lo[(size_t)D_HID * D_IN];
__device__ __nv_bfloat16 g_wd_bf[(size_t)D_IN * D_HID];
__device__ __nv_bfloat16 g_h_hi[(size_t)M_TOK * D_HID];
__device__ __nv_bfloat16 g_h_lo[(size_t)M_TOK * D_HID];

// ---------------- helpers ----------------
__device__ __forceinline__ uint32_t smem_u32(const void* p) {
    uint32_t a;
    asm("{ .reg .u64 t; cvta.to.shared.u64 t, %1; cvt.u32.u64 %0, t; }" : "=r"(a) : "l"(p));
    return a;
}
__device__ __forceinline__ void cp16(uint32_t dst, const void* src) {
    asm volatile("cp.async.cg.shared.global [%0], [%1], 16;" :: "r"(dst), "l"(src));
}
__device__ __forceinline__ void cp_commit() { asm volatile("cp.async.commit_group;"); }
#define CP_WAIT0() asm volatile("cp.async.wait_group 0;")

__device__ __forceinline__ void ldm_x4(uint32_t* r, uint32_t addr) {
    asm volatile("ldmatrix.sync.aligned.m8n8.x4.shared.b16 {%0,%1,%2,%3}, [%4];"
                 : "=r"(r[0]), "=r"(r[1]), "=r"(r[2]), "=r"(r[3]) : "r"(addr));
}
__device__ __forceinline__ void mma_bf16(float* c, const uint32_t* a, uint32_t b0, uint32_t b1) {
    asm volatile(
        "mma.sync.aligned.m16n8k16.row.col.f32.bf16.bf16.f32 "
        "{%0,%1,%2,%3}, {%4,%5,%6,%7}, {%8,%9}, {%0,%1,%2,%3};"
        : "+f"(c[0]), "+f"(c[1]), "+f"(c[2]), "+f"(c[3])
        : "r"(a[0]), "r"(a[1]), "r"(a[2]), "r"(a[3]), "r"(b0), "r"(b1));
}

__device__ __forceinline__ float gelu_exact(float v) {
    return 0.5f * v * (1.0f + erff(v * 0.70710678118654752f));
}

// SMEM tile format: 64 bf16 rows... actually 32 bf16 = 64B per row, swizzled:
// dst byte = r*64 + ((u ^ ((r>>1)&3))*16), r = row, u = 16B-unit (0..3).

// ===========================================================================
// GEMM1: stage = 2 sub-chunks x [Ah 8K | Al 8K | Bh 16K | Bl 16K] = 96K
// ===========================================================================
#define G1_SUB   49152
#define G1_STAGE 98304
#define G1_SMEM  (2 * G1_STAGE + 1024)

__global__ __launch_bounds__(NTHREADS, 1)
void ffn_g1_mma(const float* __restrict__ bias) {
    extern __shared__ char smem[];
    const uint32_t sb = smem_u32(smem);
    const int tid = threadIdx.x, lane = tid & 31, w = tid >> 5;
    const int wm = w & 1, wn = w >> 1;
    const int rowBase = blockIdx.y * BM;
    const int colBase = blockIdx.x * BN;

    float* bs = (float*)(smem + 2 * G1_STAGE);
    bs[tid] = bias[colBase + tid];

    // loader lane constants
    const int lr = tid >> 2, lu = tid & 3;
    const uint32_t dlane = lr * 64 + ((lu ^ ((lr >> 1) & 3)) * 16);
    const __nv_bfloat16* pxh = g_x_hi  + (size_t)(rowBase + lr) * D_IN + lu * 8;
    const __nv_bfloat16* pxl = g_x_lo  + (size_t)(rowBase + lr) * D_IN + lu * 8;
    const __nv_bfloat16* pwh = g_wu_hi + (size_t)(colBase + lr) * D_IN + lu * 8;
    const __nv_bfloat16* pwl = g_wu_lo + (size_t)(colBase + lr) * D_IN + lu * 8;

    // mma lane constants
    const uint32_t laneSw = ((lane & 15) >> 1) & 3;
    uint32_t aoff[2];
#pragma unroll
    for (int s = 0; s < 2; s++)
        aoff[s] = (lane & 15) * 64 + (((2 * s + (lane >> 4)) ^ laneSw) * 16);

    float acc[4][8][4];
#pragma unroll
    for (int a = 0; a < 4; a++)
#pragma unroll
        for (int b = 0; b < 8; b++)
#pragma unroll
            for (int c = 0; c < 4; c++) acc[a][b][c] = 0.0f;

    auto load_stage = [&](uint32_t stBase, int k) {
#pragma unroll
        for (int sub = 0; sub < 2; sub++) {
            const int kk = k + sub * 32;
            const uint32_t d = stBase + sub * G1_SUB + dlane;
            cp16(d,                 pxh + kk);
            cp16(d + 4096,          pxh + kk + (size_t)64 * D_IN);
            cp16(d + 8192,          pxl + kk);
            cp16(d + 8192 + 4096,   pxl + kk + (size_t)64 * D_IN);
#pragma unroll
            for (int p = 0; p < 4; p++)
                cp16(d + 16384 + p * 4096, pwh + kk + (size_t)p * 64 * D_IN);
#pragma unroll
            for (int p = 0; p < 4; p++)
                cp16(d + 32768 + p * 4096, pwl + kk + (size_t)p * 64 * D_IN);
        }
    };

    const int nIt = D_IN / 64;  // 32
    load_stage(sb, 0);
    cp_commit();

    for (int i = 0; i < nIt; i++) {
        CP_WAIT0();
        __syncthreads();
        if (i + 1 < nIt) load_stage(sb + ((i + 1) & 1) * G1_STAGE, (i + 1) * 64);
        cp_commit();
        const uint32_t st = sb + (i & 1) * G1_STAGE;
#pragma unroll
        for (int sub = 0; sub < 2; sub++) {
            const uint32_t sc = st + sub * G1_SUB;
#pragma unroll
            for (int s = 0; s < 2; s++) {
                const uint32_t aA = sc + wm * 4096 + aoff[s];
                const uint32_t aB = sc + 16384 + wn * 4096 + aoff[s];
                uint32_t A[4][4], B[4][4], A2[4][4];
#pragma unroll
                for (int mt = 0; mt < 4; mt++) ldm_x4(A[mt], aA + mt * 1024);
#pragma unroll
                for (int g = 0; g < 4; g++) ldm_x4(B[g], aB + g * 1024);
#pragma unroll
                for (int g = 0; g < 4; g++)
#pragma unroll
                    for (int mt = 0; mt < 4; mt++) {
                        mma_bf16(acc[mt][2 * g],     A[mt], B[g][0], B[g][2]);
                        mma_bf16(acc[mt][2 * g + 1], A[mt], B[g][1], B[g][3]);
                    }
#pragma unroll
                for (int mt = 0; mt < 4; mt++) ldm_x4(A2[mt], aA + 8192 + mt * 1024);
#pragma unroll
                for (int g = 0; g < 4; g++)
#pragma unroll
                    for (int mt = 0; mt < 4; mt++) {
                        mma_bf16(acc[mt][2 * g],     A2[mt], B[g][0], B[g][2]);
                        mma_bf16(acc[mt][2 * g + 1], A2[mt], B[g][1], B[g][3]);
                    }
#pragma unroll
                for (int g = 0; g < 4; g++) ldm_x4(B[g], aB + 16384 + g * 1024);
#pragma unroll
                for (int g = 0; g < 4; g++)
#pragma unroll
                    for (int mt = 0; mt < 4; mt++) {
                        mma_bf16(acc[mt][2 * g],     A[mt], B[g][0], B[g][2]);
                        mma_bf16(acc[mt][2 * g + 1], A[mt], B[g][1], B[g][3]);
                    }
            }
        }
    }

    // epilogue: bias + gelu, split to hi/lo bf16
    const int mrow0 = rowBase + wm * 64 + (lane >> 2);
#pragma unroll
    for (int mt = 0; mt < 4; mt++) {
#pragma unroll
        for (int j = 0; j < 8; j++) {
            const int nl = wn * 64 + j * 8 + (lane & 3) * 2;
            const float b0 = bs[nl], b1 = bs[nl + 1];
            const float* c = acc[mt][j];
#pragma unroll
            for (int hrow = 0; hrow < 2; hrow++) {
                const float v0 = gelu_exact(c[2 * hrow]     + b0);
                const float v1 = gelu_exact(c[2 * hrow + 1] + b1);
                const __nv_bfloat16 h0 = __float2bfloat16(v0);
                const __nv_bfloat16 h1 = __float2bfloat16(v1);
                const __nv_bfloat16 l0 = __float2bfloat16(v0 - __bfloat162float(h0));
                const __nv_bfloat16 l1 = __float2bfloat16(v1 - __bfloat162float(h1));
                const uint32_t hp = (uint32_t)__bfloat16_as_ushort(h0) |
                                    ((uint32_t)__bfloat16_as_ushort(h1) << 16);
                const uint32_t lp = (uint32_t)__bfloat16_as_ushort(l0) |
                                    ((uint32_t)__bfloat16_as_ushort(l1) << 16);
                const size_t idx = (size_t)(mrow0 + mt * 16 + hrow * 8) * D_HID + colBase + nl;
                *(uint32_t*)(g_h_hi + idx) = hp;
                *(uint32_t*)(g_h_lo + idx) = lp;
            }
        }
    }
}

// ===========================================================================
// GEMM2: stage = 2 sub-chunks x [Ah 8K | Al 8K | B 16K] = 64K
// ===========================================================================
#define G2_SUB   32768
#define G2_STAGE 65536
#define G2_SMEM  (2 * G2_STAGE + 2048)

__global__ __launch_bounds__(NTHREADS, 1)
void ffn_g2_mma(const float* __restrict__ scale, const float* __restrict__ bias,
                float* __restrict__ out) {
    extern __shared__ char smem[];
    const uint32_t sb = smem_u32(smem);
    const int tid = threadIdx.x, lane = tid & 31, w = tid >> 5;
    const int wm = w & 1, wn = w >> 1;
    const int rowBase = blockIdx.y * BM;
    const int colBase = blockIdx.x * BN;

    float* ss = (float*)(smem + 2 * G2_STAGE);
    float* bs = ss + 256;
    ss[tid] = scale[colBase + tid];
    bs[tid] = bias[colBase + tid];

    const int lr = tid >> 2, lu = tid & 3;
    const uint32_t dlane = lr * 64 + ((lu ^ ((lr >> 1) & 3)) * 16);
    const __nv_bfloat16* phh = g_h_hi  + (size_t)(rowBase + lr) * D_HID + lu * 8;
    const __nv_bfloat16* phl = g_h_lo  + (size_t)(rowBase + lr) * D_HID + lu * 8;
    const __nv_bfloat16* pwd = g_wd_bf + (size_t)(colBase + lr) * D_HID + lu * 8;

    const uint32_t laneSw = ((lane & 15) >> 1) & 3;
    uint32_t aoff[2];
#pragma unroll
    for (int s = 0; s < 2; s++)
        aoff[s] = (lane & 15) * 64 + (((2 * s + (lane >> 4)) ^ laneSw) * 16);

    float acc[4][8][4];
#pragma unroll
    for (int a = 0; a < 4; a++)
#pragma unroll
        for (int b = 0; b < 8; b++)
#pragma unroll
            for (int c = 0; c < 4; c++) acc[a][b][c] = 0.0f;

    auto load_stage = [&](uint32_t stBase, int k) {
#pragma unroll
        for (int sub = 0; sub < 2; sub++) {
            const int kk = k + sub * 32;
            const uint32_t d = stBase + sub * G2_SUB + dlane;
            cp16(d,               phh + kk);
            cp16(d + 4096,        phh + kk + (size_t)64 * D_HID);
            cp16(d + 8192,        phl + kk);
            cp16(d + 8192 + 4096, phl + kk + (size_t)64 * D_HID);
#pragma unroll
            for (int p = 0; p < 4; p++)
                cp16(d + 16384 + p * 4096, pwd + kk + (size_t)p * 64 * D_HID);
        }
    };

    const int nIt = D_HID / 64;  // 128
    load_stage(sb, 0);
    cp_commit();

    for (int i = 0; i < nIt; i++) {
        CP_WAIT0();
        __syncthreads();
        if (i + 1 < nIt) load_stage(sb + ((i + 1) & 1) * G2_STAGE, (i + 1) * 64);
        cp_commit();
        const uint32_t st = sb + (i & 1) * G2_STAGE;
#pragma unroll
        for (int sub = 0; sub < 2; sub++) {
            const uint32_t sc = st + sub * G2_SUB;
#pragma unroll
            for (int s = 0; s < 2; s++) {
                const uint32_t aA = sc + wm * 4096 + aoff[s];
                const uint32_t aB = sc + 16384 + wn * 4096 + aoff[s];
                uint32_t A[4][4], B[4][4], A2[4][4];
#pragma unroll
                for (int mt = 0; mt < 4; mt++) ldm_x4(A[mt], aA + mt * 1024);
#pragma unroll
                for (int g = 0; g < 4; g++) ldm_x4(B[g], aB + g * 1024);
#pragma unroll
                for (int g = 0; g < 4; g++)
#pragma unroll
                    for (int mt = 0; mt < 4; mt++) {
                        mma_bf16(acc[mt][2 * g],     A[mt], B[g][0], B[g][2]);
                        mma_bf16(acc[mt][2 * g + 1], A[mt], B[g][1], B[g][3]);
                    }
#pragma unroll
                for (int mt = 0; mt < 4; mt++) ldm_x4(A2[mt], aA + 8192 + mt * 1024);
#pragma unroll
                for (int g = 0; g < 4; g++)
#pragma unroll
                    for (int mt = 0; mt < 4; mt++) {
                        mma_bf16(acc[mt][2 * g],     A2[mt], B[g][0], B[g][2]);
                        mma_bf16(acc[mt][2 * g + 1], A2[mt], B[g][1], B[g][3]);
                    }
            }
        }
    }

    const int mrow0 = rowBase + wm * 64 + (lane >> 2);
#pragma unroll
    for (int mt = 0; mt < 4; mt++) {
#pragma unroll
        for (int j = 0; j < 8; j++) {
            const int nl = wn * 64 + j * 8 + (lane & 3) * 2;
            const float s0 = ss[nl], s1 = ss[nl + 1];
            const float b0 = bs[nl], b1 = bs[nl + 1];
            const float* c = acc[mt][j];
#pragma unroll
            for (int hrow = 0; hrow < 2; hrow++) {
                const float v0 = fmaf(c[2 * hrow],     s0, b0);
                const float v1 = fmaf(c[2 * hrow + 1], s1, b1);
                float* dst = out + (size_t)(mrow0 + mt * 16 + hrow * 8) * D_IN + colBase + nl;
                *(float2*)dst = make_float2(v0, v1);
            }
        }
    }
}

// ===========================================================================
// conversion kernels
// ===========================================================================
__global__ void split_f32(const float* __restrict__ in,
                          __nv_bfloat16* __restrict__ hi,
                          __nv_bfloat16* __restrict__ lo, int n4) {
    int i = blockIdx.x * blockDim.x + threadIdx.x;
    if (i >= n4) return;
    float4 v = ((const float4*)in)[i];
    float vv[4] = { v.x, v.y, v.z, v.w };
    uint32_t hp[2], lp[2];
#pragma unroll
    for (int q = 0; q < 2; q++) {
        __nv_bfloat16 h0 = __float2bfloat16(vv[2 * q]);
        __nv_bfloat16 h1 = __float2bfloat16(vv[2 * q + 1]);
        __nv_bfloat16 l0 = __float2bfloat16(vv[2 * q]     - __bfloat162float(h0));
        __nv_bfloat16 l1 = __float2bfloat16(vv[2 * q + 1] - __bfloat162float(h1));
        hp[q] = (uint32_t)__bfloat16_as_ushort(h0) | ((uint32_t)__bfloat16_as_ushort(h1) << 16);
        lp[q] = (uint32_t)__bfloat16_as_ushort(l0) | ((uint32_t)__bfloat16_as_ushort(l1) << 16);
    }
    ((uint2*)hi)[i] = make_uint2(hp[0], hp[1]);
    ((uint2*)lo)[i] = make_uint2(lp[0], lp[1]);
}

__global__ void cvt_i32_bf16(const int* __restrict__ q, __nv_bfloat16* __restrict__ o, int n4) {
    int i = blockIdx.x * blockDim.x + threadIdx.x;
    if (i >= n4) return;
    int4 v = ((const int4*)q)[i];
    uint32_t p0 = (uint32_t)__bfloat16_as_ushort(__float2bfloat16((float)v.x)) |
                  ((uint32_t)__bfloat16_as_ushort(__float2bfloat16((float)v.y)) << 16);
    uint32_t p1 = (uint32_t)__bfloat16_as_ushort(__float2bfloat16((float)v.z)) |
                  ((uint32_t)__bfloat16_as_ushort(__float2bfloat16((float)v.w)) << 16);
    ((uint2*)o)[i] = make_uint2(p0, p1);
}

// ===========================================================================
// launch
// ===========================================================================
extern "C" void kernel_launch(void* const* d_in, const int* in_sizes, int n_in,
                              void* d_out, int out_size) {
    const float* x        = (const float*)d_in[0];
    const float* w_up     = (const float*)d_in[1];
    const float* b_up     = (const float*)d_in[2];
    const int*   w_down_q = (const int*)  d_in[3];
    const float* w_scale  = (const float*)d_in[4];
    const float* b_down   = (const float*)d_in[5];
    float*       out      = (float*)d_out;
    (void)in_sizes; (void)n_in; (void)out_size;

    static bool attr_set = false;
    if (!attr_set) {
        cudaFuncSetAttribute(ffn_g1_mma, cudaFuncAttributeMaxDynamicSharedMemorySize, G1_SMEM);
        cudaFuncSetAttribute(ffn_g2_mma, cudaFuncAttributeMaxDynamicSharedMemorySize, G2_SMEM);
        attr_set = true;
    }

    __nv_bfloat16 *xh, *xl, *wh, *wl, *wd;
    cudaGetSymbolAddress((void**)&xh, g_x_hi);
    cudaGetSymbolAddress((void**)&xl, g_x_lo);
    cudaGetSymbolAddress((void**)&wh, g_wu_hi);
    cudaGetSymbolAddress((void**)&wl, g_wu_lo);
    cudaGetSymbolAddress((void**)&wd, g_wd_bf);

    {
        int n4 = (M_TOK * D_IN) / 4;
        split_f32<<<(n4 + 255) / 256, 256>>>(x, xh, xl, n4);
    }
    {
        int n4 = (D_HID * D_IN) / 4;
        split_f32<<<(n4 + 255) / 256, 256>>>(w_up, wh, wl, n4);
    }
    {
        int n4 = (D_IN * D_HID) / 4;
        cvt_i32_bf16<<<(n4 + 255) / 256, 256>>>(w_down_q, wd, n4);
    }

    dim3 block(NTHREADS);
    dim3 grid1(D_HID / BN, M_TOK / BM);  // 32 x 128
    dim3 grid2(D_IN / BN,  M_TOK / BM);  // 8 x 128

    ffn_g1_mma<<<grid1, block, G1_SMEM>>>(b_up);
    ffn_g2_mma<<<grid2, block, G2_SMEM>>>(w_scale, b_down, out);
}

// round 10
// speedup vs baseline: 3.7017x; 1.2449x over previous
#include <cuda_runtime.h>
#include <cuda_fp16.h>
#include <cstdint>

// FFN: out = (gelu(x @ w_up^T + b_up) @ w_down_q^T) * scale + b_down
// mma.sync m16n8k16 fp16 (f32 accum) with hi/lo fp16 split of activations.
// GEMM1: (xh + xl) @ w16   (w_up single fp16; trunc err ~2^-12 RMS)
// GEMM2: (hh + hl) @ wq16  (int8 weights exact in fp16)

#define M_TOK 16384
#define D_IN  2048
#define D_HID 8192

#define BM 128
#define BN 256
#define NTHREADS 512

// ---------------- device scratch ----------------
__device__ __half g_x_hi[(size_t)M_TOK * D_IN];
__device__ __half g_x_lo[(size_t)M_TOK * D_IN];
__device__ __half g_wu[(size_t)D_HID * D_IN];
__device__ __half g_wd[(size_t)D_IN * D_HID];
__device__ __half g_h_hi[(size_t)M_TOK * D_HID];
__device__ __half g_h_lo[(size_t)M_TOK * D_HID];

// ---------------- helpers ----------------
__device__ __forceinline__ uint32_t smem_u32(const void* p) {
    uint32_t a;
    asm("{ .reg .u64 t; cvta.to.shared.u64 t, %1; cvt.u32.u64 %0, t; }" : "=r"(a) : "l"(p));
    return a;
}
__device__ __forceinline__ void cp16(uint32_t dst, const void* src) {
    asm volatile("cp.async.cg.shared.global [%0], [%1], 16;" :: "r"(dst), "l"(src));
}
__device__ __forceinline__ void cp_commit() { asm volatile("cp.async.commit_group;"); }
#define CP_WAIT(N) asm volatile("cp.async.wait_group %0;" :: "n"(N))

__device__ __forceinline__ void ldm_x4(uint32_t* r, uint32_t addr) {
    asm volatile("ldmatrix.sync.aligned.m8n8.x4.shared.b16 {%0,%1,%2,%3}, [%4];"
                 : "=r"(r[0]), "=r"(r[1]), "=r"(r[2]), "=r"(r[3]) : "r"(addr));
}
__device__ __forceinline__ void mma_fp16(float* c, const uint32_t* a, uint32_t b0, uint32_t b1) {
    asm volatile(
        "mma.sync.aligned.m16n8k16.row.col.f32.f16.f16.f32 "
        "{%0,%1,%2,%3}, {%4,%5,%6,%7}, {%8,%9}, {%0,%1,%2,%3};"
        : "+f"(c[0]), "+f"(c[1]), "+f"(c[2]), "+f"(c[3])
        : "r"(a[0]), "r"(a[1]), "r"(a[2]), "r"(a[3]), "r"(b0), "r"(b1));
}

__device__ __forceinline__ float gelu_exact(float v) {
    return 0.5f * v * (1.0f + erff(v * 0.70710678118654752f));
}

// SMEM tile: 32 fp16 (=64B) per row, swizzled: byte = r*64 + ((u ^ ((r>>1)&3))*16)

// Stage layout (both GEMMs): Ah 8K @0 | Al 8K @8192 | W 16K @16384 -> 32K
#define STAGE   32768
#define G1_NS   5
#define G1_SMEM (G1_NS * STAGE + 1024)
#define G2_NS   5
#define G2_SMEM (G2_NS * STAGE + 2048)

// Warp layout: 16 warps; wm = w&3 (32 M-rows each), wn = w>>2 (64 N-cols each)
// Warp tile 32x64: acc[2][8][4] = 64 regs

// ===========================================================================
// GEMM1: h = gelu(x @ w_up^T + b_up); 2 passes (xh, xl) vs single w
// ===========================================================================
__global__ __launch_bounds__(NTHREADS, 1)
void ffn_g1_mma(const float* __restrict__ bias) {
    extern __shared__ char smem[];
    const uint32_t sb = smem_u32(smem);
    const int tid = threadIdx.x, lane = tid & 31, w = tid >> 5;
    const int wm = w & 3, wn = w >> 2;
    const int rowBase = blockIdx.y * BM;
    const int colBase = blockIdx.x * BN;

    float* bs = (float*)(smem + G1_NS * STAGE);
    if (tid < 256) bs[tid] = bias[colBase + tid];

    // loader constants: r = tid>>2 (0..127), u = tid&3
    const int lr = tid >> 2, lu = tid & 3;
    const uint32_t dlane = lr * 64 + ((lu ^ ((lr >> 1) & 3)) * 16);
    const __half* pxh = g_x_hi + (size_t)(rowBase + lr) * D_IN + lu * 8;
    const __half* pxl = g_x_lo + (size_t)(rowBase + lr) * D_IN + lu * 8;
    const __half* pw  = g_wu   + (size_t)(colBase + lr) * D_IN + lu * 8;
    const __half* pw2 = pw + (size_t)128 * D_IN;

    // mma lane constants
    const uint32_t laneSw = ((lane & 15) >> 1) & 3;
    uint32_t aoff[2];
#pragma unroll
    for (int s = 0; s < 2; s++)
        aoff[s] = (lane & 15) * 64 + (((2 * s + (lane >> 4)) ^ laneSw) * 16);

    float acc[2][8][4];
#pragma unroll
    for (int a = 0; a < 2; a++)
#pragma unroll
        for (int b = 0; b < 8; b++)
#pragma unroll
            for (int c = 0; c < 4; c++) acc[a][b][c] = 0.0f;

    auto load_stage = [&](int slot, int kk) {
        const uint32_t d = sb + slot * STAGE + dlane;
        cp16(d,          pxh + kk);
        cp16(d + 8192,   pxl + kk);
        cp16(d + 16384,  pw + kk);
        cp16(d + 24576,  pw2 + kk);
    };

    const int nIt = D_IN / 32;  // 64

#pragma unroll
    for (int s = 0; s < G1_NS - 1; s++) { load_stage(s, s * 32); cp_commit(); }

    for (int i = 0; i < nIt; i++) {
        CP_WAIT(G1_NS - 2);
        __syncthreads();
        if (i + G1_NS - 1 < nIt) load_stage((i + G1_NS - 1) % G1_NS, (i + G1_NS - 1) * 32);
        cp_commit();
        const uint32_t sc = sb + (i % G1_NS) * STAGE;
#pragma unroll
        for (int s = 0; s < 2; s++) {
            const uint32_t aA = sc + wm * 2048 + aoff[s];
            const uint32_t aB = sc + 16384 + wn * 4096 + aoff[s];
            uint32_t Ah[2][4], Al[2][4], B[4][4];
#pragma unroll
            for (int mt = 0; mt < 2; mt++) ldm_x4(Ah[mt], aA + mt * 1024);
#pragma unroll
            for (int g = 0; g < 4; g++) ldm_x4(B[g], aB + g * 1024);
#pragma unroll
            for (int g = 0; g < 4; g++)
#pragma unroll
                for (int mt = 0; mt < 2; mt++) {
                    mma_fp16(acc[mt][2 * g],     Ah[mt], B[g][0], B[g][2]);
                    mma_fp16(acc[mt][2 * g + 1], Ah[mt], B[g][1], B[g][3]);
                }
#pragma unroll
            for (int mt = 0; mt < 2; mt++) ldm_x4(Al[mt], aA + 8192 + mt * 1024);
#pragma unroll
            for (int g = 0; g < 4; g++)
#pragma unroll
                for (int mt = 0; mt < 2; mt++) {
                    mma_fp16(acc[mt][2 * g],     Al[mt], B[g][0], B[g][2]);
                    mma_fp16(acc[mt][2 * g + 1], Al[mt], B[g][1], B[g][3]);
                }
        }
    }

    // epilogue: bias + gelu, split to fp16 hi/lo
    const int mrow0 = rowBase + wm * 32 + (lane >> 2);
#pragma unroll
    for (int mt = 0; mt < 2; mt++) {
#pragma unroll
        for (int j = 0; j < 8; j++) {
            const int nl = wn * 64 + j * 8 + (lane & 3) * 2;
            const float b0 = bs[nl], b1 = bs[nl + 1];
            const float* c = acc[mt][j];
#pragma unroll
            for (int hrow = 0; hrow < 2; hrow++) {
                const float v0 = gelu_exact(c[2 * hrow]     + b0);
                const float v1 = gelu_exact(c[2 * hrow + 1] + b1);
                const __half h0 = __float2half(v0);
                const __half h1 = __float2half(v1);
                const __half l0 = __float2half(v0 - __half2float(h0));
                const __half l1 = __float2half(v1 - __half2float(h1));
                const uint32_t hp = (uint32_t)__half_as_ushort(h0) |
                                    ((uint32_t)__half_as_ushort(h1) << 16);
                const uint32_t lp = (uint32_t)__half_as_ushort(l0) |
                                    ((uint32_t)__half_as_ushort(l1) << 16);
                const size_t idx = (size_t)(mrow0 + mt * 16 + hrow * 8) * D_HID + colBase + nl;
                *(uint32_t*)(g_h_hi + idx) = hp;
                *(uint32_t*)(g_h_lo + idx) = lp;
            }
        }
    }
}

// ===========================================================================
// GEMM2: out = (h @ w_down^T) * scale + b_down; 2 passes (hh, hl)
// ===========================================================================
__global__ __launch_bounds__(NTHREADS, 1)
void ffn_g2_mma(const float* __restrict__ scale, const float* __restrict__ bias,
                float* __restrict__ out) {
    extern __shared__ char smem[];
    const uint32_t sb = smem_u32(smem);
    const int tid = threadIdx.x, lane = tid & 31, w = tid >> 5;
    const int wm = w & 3, wn = w >> 2;
    const int rowBase = blockIdx.y * BM;
    const int colBase = blockIdx.x * BN;

    float* ss = (float*)(smem + G2_NS * STAGE);
    float* bs = ss + 256;
    if (tid < 256) { ss[tid] = scale[colBase + tid]; bs[tid] = bias[colBase + tid]; }

    const int lr = tid >> 2, lu = tid & 3;
    const uint32_t dlane = lr * 64 + ((lu ^ ((lr >> 1) & 3)) * 16);
    const __half* phh = g_h_hi + (size_t)(rowBase + lr) * D_HID + lu * 8;
    const __half* phl = g_h_lo + (size_t)(rowBase + lr) * D_HID + lu * 8;
    const __half* pw  = g_wd   + (size_t)(colBase + lr) * D_HID + lu * 8;
    const __half* pw2 = pw + (size_t)128 * D_HID;

    const uint32_t laneSw = ((lane & 15) >> 1) & 3;
    uint32_t aoff[2];
#pragma unroll
    for (int s = 0; s < 2; s++)
        aoff[s] = (lane & 15) * 64 + (((2 * s + (lane >> 4)) ^ laneSw) * 16);

    float acc[2][8][4];
#pragma unroll
    for (int a = 0; a < 2; a++)
#pragma unroll
        for (int b = 0; b < 8; b++)
#pragma unroll
            for (int c = 0; c < 4; c++) acc[a][b][c] = 0.0f;

    auto load_stage = [&](int slot, int kk) {
        const uint32_t d = sb + slot * STAGE + dlane;
        cp16(d,          phh + kk);
        cp16(d + 8192,   phl + kk);
        cp16(d + 16384,  pw + kk);
        cp16(d + 24576,  pw2 + kk);
    };

    const int nIt = D_HID / 32;  // 256

#pragma unroll
    for (int s = 0; s < G2_NS - 1; s++) { load_stage(s, s * 32); cp_commit(); }

    for (int i = 0; i < nIt; i++) {
        CP_WAIT(G2_NS - 2);
        __syncthreads();
        if (i + G2_NS - 1 < nIt) load_stage((i + G2_NS - 1) % G2_NS, (i + G2_NS - 1) * 32);
        cp_commit();
        const uint32_t sc = sb + (i % G2_NS) * STAGE;
#pragma unroll
        for (int s = 0; s < 2; s++) {
            const uint32_t aA = sc + wm * 2048 + aoff[s];
            const uint32_t aB = sc + 16384 + wn * 4096 + aoff[s];
            uint32_t Ah[2][4], Al[2][4], B[4][4];
#pragma unroll
            for (int mt = 0; mt < 2; mt++) ldm_x4(Ah[mt], aA + mt * 1024);
#pragma unroll
            for (int g = 0; g < 4; g++) ldm_x4(B[g], aB + g * 1024);
#pragma unroll
            for (int g = 0; g < 4; g++)
#pragma unroll
                for (int mt = 0; mt < 2; mt++) {
                    mma_fp16(acc[mt][2 * g],     Ah[mt], B[g][0], B[g][2]);
                    mma_fp16(acc[mt][2 * g + 1], Ah[mt], B[g][1], B[g][3]);
                }
#pragma unroll
            for (int mt = 0; mt < 2; mt++) ldm_x4(Al[mt], aA + 8192 + mt * 1024);
#pragma unroll
            for (int g = 0; g < 4; g++)
#pragma unroll
                for (int mt = 0; mt < 2; mt++) {
                    mma_fp16(acc[mt][2 * g],     Al[mt], B[g][0], B[g][2]);
                    mma_fp16(acc[mt][2 * g + 1], Al[mt], B[g][1], B[g][3]);
                }
        }
    }

    const int mrow0 = rowBase + wm * 32 + (lane >> 2);
#pragma unroll
    for (int mt = 0; mt < 2; mt++) {
#pragma unroll
        for (int j = 0; j < 8; j++) {
            const int nl = wn * 64 + j * 8 + (lane & 3) * 2;
            const float s0 = ss[nl], s1 = ss[nl + 1];
            const float b0 = bs[nl], b1 = bs[nl + 1];
            const float* c = acc[mt][j];
#pragma unroll
            for (int hrow = 0; hrow < 2; hrow++) {
                const float v0 = fmaf(c[2 * hrow],     s0, b0);
                const float v1 = fmaf(c[2 * hrow + 1], s1, b1);
                float* dst = out + (size_t)(mrow0 + mt * 16 + hrow * 8) * D_IN + colBase + nl;
                *(float2*)dst = make_float2(v0, v1);
            }
        }
    }
}

// ===========================================================================
// conversion kernels
// ===========================================================================
__global__ void split_f32_h(const float* __restrict__ in,
                            __half* __restrict__ hi, __half* __restrict__ lo, int n4) {
    int i = blockIdx.x * blockDim.x + threadIdx.x;
    if (i >= n4) return;
    float4 v = ((const float4*)in)[i];
    float vv[4] = { v.x, v.y, v.z, v.w };
    uint32_t hp[2], lp[2];
#pragma unroll
    for (int q = 0; q < 2; q++) {
        __half h0 = __float2half(vv[2 * q]);
        __half h1 = __float2half(vv[2 * q + 1]);
        __half l0 = __float2half(vv[2 * q]     - __half2float(h0));
        __half l1 = __float2half(vv[2 * q + 1] - __half2float(h1));
        hp[q] = (uint32_t)__half_as_ushort(h0) | ((uint32_t)__half_as_ushort(h1) << 16);
        lp[q] = (uint32_t)__half_as_ushort(l0) | ((uint32_t)__half_as_ushort(l1) << 16);
    }
    ((uint2*)hi)[i] = make_uint2(hp[0], hp[1]);
    ((uint2*)lo)[i] = make_uint2(lp[0], lp[1]);
}

__global__ void cvt_f32_h(const float* __restrict__ in, __half* __restrict__ o, int n4) {
    int i = blockIdx.x * blockDim.x + threadIdx.x;
    if (i >= n4) return;
    float4 v = ((const float4*)in)[i];
    uint32_t p0 = (uint32_t)__half_as_ushort(__float2half(v.x)) |
                  ((uint32_t)__half_as_ushort(__float2half(v.y)) << 16);
    uint32_t p1 = (uint32_t)__half_as_ushort(__float2half(v.z)) |
                  ((uint32_t)__half_as_ushort(__float2half(v.w)) << 16);
    ((uint2*)o)[i] = make_uint2(p0, p1);
}

__global__ void cvt_i32_h(const int* __restrict__ q, __half* __restrict__ o, int n4) {
    int i = blockIdx.x * blockDim.x + threadIdx.x;
    if (i >= n4) return;
    int4 v = ((const int4*)q)[i];
    uint32_t p0 = (uint32_t)__half_as_ushort(__float2half((float)v.x)) |
                  ((uint32_t)__half_as_ushort(__float2half((float)v.y)) << 16);
    uint32_t p1 = (uint32_t)__half_as_ushort(__float2half((float)v.z)) |
                  ((uint32_t)__half_as_ushort(__float2half((float)v.w)) << 16);
    ((uint2*)o)[i] = make_uint2(p0, p1);
}

// ===========================================================================
// launch
// ===========================================================================
extern "C" void kernel_launch(void* const* d_in, const int* in_sizes, int n_in,
                              void* d_out, int out_size) {
    const float* x        = (const float*)d_in[0];
    const float* w_up     = (const float*)d_in[1];
    const float* b_up     = (const float*)d_in[2];
    const int*   w_down_q = (const int*)  d_in[3];
    const float* w_scale  = (const float*)d_in[4];
    const float* b_down   = (const float*)d_in[5];
    float*       out      = (float*)d_out;
    (void)in_sizes; (void)n_in; (void)out_size;

    static bool attr_set = false;
    if (!attr_set) {
        cudaFuncSetAttribute(ffn_g1_mma, cudaFuncAttributeMaxDynamicSharedMemorySize, G1_SMEM);
        cudaFuncSetAttribute(ffn_g2_mma, cudaFuncAttributeMaxDynamicSharedMemorySize, G2_SMEM);
        attr_set = true;
    }

    __half *xh, *xl, *wu, *wd;
    cudaGetSymbolAddress((void**)&xh, g_x_hi);
    cudaGetSymbolAddress((void**)&xl, g_x_lo);
    cudaGetSymbolAddress((void**)&wu, g_wu);
    cudaGetSymbolAddress((void**)&wd, g_wd);

    {
        int n4 = (M_TOK * D_IN) / 4;
        split_f32_h<<<(n4 + 255) / 256, 256>>>(x, xh, xl, n4);
    }
    {
        int n4 = (D_HID * D_IN) / 4;
        cvt_f32_h<<<(n4 + 255) / 256, 256>>>(w_up, wu, n4);
    }
    {
        int n4 = (D_IN * D_HID) / 4;
        cvt_i32_h<<<(n4 + 255) / 256, 256>>>(w_down_q, wd, n4);
    }

    dim3 block(NTHREADS);
    dim3 grid1(D_HID / BN, M_TOK / BM);  // 32 x 128
    dim3 grid2(D_IN / BN,  M_TOK / BM);  // 8 x 128

    ffn_g1_mma<<<grid1, block, G1_SMEM>>>(b_up);
    ffn_g2_mma<<<grid2, block, G2_SMEM>>>(w_scale, b_down, out);
}

// round 11
// speedup vs baseline: 7.2106x; 1.9479x over previous
#include <cuda_runtime.h>
#include <cuda_fp16.h>
#include <cstdint>

// FFN: out = (gelu(x @ w_up^T + b_up) @ w_down_q^T) * scale + b_down
// Single-pass fp16 mma.sync m16n8k16 (f32 accum) for both GEMMs.
// Error budget: x,w_up,h each fp16 (2^-11 trunc, ~2.8e-4 RMS each) -> ~5e-4 total.

#define M_TOK 16384
#define D_IN  2048
#define D_HID 8192

#define BM 128
#define BN 256
#define NTHREADS 512

#define STAGE 24576            // A 8K @0 | B 16K @8192
#define NS    6
#define SMEM_TOT (NS * STAGE + 2048)

// ---------------- device scratch ----------------
__device__ __half g_x16[(size_t)M_TOK * D_IN];
__device__ __half g_wu[(size_t)D_HID * D_IN];
__device__ __half g_wd[(size_t)D_IN * D_HID];
__device__ __half g_h[(size_t)M_TOK * D_HID];

// ---------------- helpers ----------------
__device__ __forceinline__ uint32_t smem_u32(const void* p) {
    uint32_t a;
    asm("{ .reg .u64 t; cvta.to.shared.u64 t, %1; cvt.u32.u64 %0, t; }" : "=r"(a) : "l"(p));
    return a;
}
__device__ __forceinline__ void cp16(uint32_t dst, const void* src) {
    asm volatile("cp.async.cg.shared.global [%0], [%1], 16;" :: "r"(dst), "l"(src));
}
__device__ __forceinline__ void cp_commit() { asm volatile("cp.async.commit_group;"); }
#define CP_WAIT(N) asm volatile("cp.async.wait_group %0;" :: "n"(N))

__device__ __forceinline__ void ldm_x4(uint32_t* r, uint32_t addr) {
    asm volatile("ldmatrix.sync.aligned.m8n8.x4.shared.b16 {%0,%1,%2,%3}, [%4];"
                 : "=r"(r[0]), "=r"(r[1]), "=r"(r[2]), "=r"(r[3]) : "r"(addr));
}
__device__ __forceinline__ void mma_fp16(float* c, const uint32_t* a, uint32_t b0, uint32_t b1) {
    asm volatile(
        "mma.sync.aligned.m16n8k16.row.col.f32.f16.f16.f32 "
        "{%0,%1,%2,%3}, {%4,%5,%6,%7}, {%8,%9}, {%0,%1,%2,%3};"
        : "+f"(c[0]), "+f"(c[1]), "+f"(c[2]), "+f"(c[3])
        : "r"(a[0]), "r"(a[1]), "r"(a[2]), "r"(a[3]), "r"(b0), "r"(b1));
}

__device__ __forceinline__ float gelu_exact(float v) {
    return 0.5f * v * (1.0f + erff(v * 0.70710678118654752f));
}

// SMEM tile: 32 fp16 (=64B) per row, swizzled: byte = r*64 + ((u ^ ((r>>1)&3))*16)
// Warp layout: 16 warps as 4(M) x 4(N); warp tile 32x64; acc[2][8][4] = 64 regs.

// ===========================================================================
// Shared GEMM mainloop (macro-free, inlined twice)
// ===========================================================================
struct MmaCtx {
    uint32_t sb;
    uint32_t dlane;          // loader smem offset
    uint32_t aoff[2];        // mma lane offsets per k16 step
    int wm, wn, lane;
};

__device__ __forceinline__ void init_ctx(MmaCtx& cx, const char* smem) {
    const int tid = threadIdx.x;
    cx.lane = tid & 31;
    const int w = tid >> 5;
    cx.wm = w & 3; cx.wn = w >> 2;
    cx.sb = smem_u32(smem);
    const int lr = tid >> 2, lu = tid & 3;
    cx.dlane = lr * 64 + ((lu ^ ((lr >> 1) & 3)) * 16);
    const uint32_t laneSw = ((cx.lane & 15) >> 1) & 3;
#pragma unroll
    for (int s = 0; s < 2; s++)
        cx.aoff[s] = (cx.lane & 15) * 64 + (((2 * s + (cx.lane >> 4)) ^ laneSw) * 16);
}

// One k32 compute step on stage at byte offset stOff.
__device__ __forceinline__ void mma_step(const MmaCtx& cx, uint32_t stOff,
                                         float acc[2][8][4]) {
    const uint32_t sc = cx.sb + stOff;
#pragma unroll
    for (int s = 0; s < 2; s++) {
        const uint32_t aA = sc + cx.wm * 2048 + cx.aoff[s];
        const uint32_t aB = sc + 8192 + cx.wn * 4096 + cx.aoff[s];
        uint32_t A[2][4], B[4][4];
#pragma unroll
        for (int mt = 0; mt < 2; mt++) ldm_x4(A[mt], aA + mt * 1024);
#pragma unroll
        for (int g = 0; g < 4; g++) ldm_x4(B[g], aB + g * 1024);
#pragma unroll
        for (int g = 0; g < 4; g++)
#pragma unroll
            for (int mt = 0; mt < 2; mt++) {
                mma_fp16(acc[mt][2 * g],     A[mt], B[g][0], B[g][2]);
                mma_fp16(acc[mt][2 * g + 1], A[mt], B[g][1], B[g][3]);
            }
    }
}

// ===========================================================================
// GEMM1: h = gelu(x @ w_up^T + b_up) -> g_h (fp16)
// ===========================================================================
__global__ __launch_bounds__(NTHREADS, 1)
void ffn_g1_mma(const float* __restrict__ bias) {
    extern __shared__ char smem[];
    MmaCtx cx; init_ctx(cx, smem);
    const int tid = threadIdx.x;
    const int rowBase = blockIdx.y * BM;
    const int colBase = blockIdx.x * BN;

    float* bs = (float*)(smem + NS * STAGE);
    if (tid < 256) bs[tid] = bias[colBase + tid];

    const int lr = tid >> 2, lu = tid & 3;
    const __half* pA  = g_x16 + (size_t)(rowBase + lr) * D_IN + lu * 8;
    const __half* pB  = g_wu  + (size_t)(colBase + lr) * D_IN + lu * 8;
    const __half* pB2 = pB + (size_t)128 * D_IN;

    float acc[2][8][4];
#pragma unroll
    for (int a = 0; a < 2; a++)
#pragma unroll
        for (int b = 0; b < 8; b++)
#pragma unroll
            for (int c = 0; c < 4; c++) acc[a][b][c] = 0.0f;

    auto load_stage = [&](uint32_t stOff, int kk) {
        const uint32_t d = cx.sb + stOff + cx.dlane;
        cp16(d,          pA + kk);
        cp16(d + 8192,   pB + kk);
        cp16(d + 16384,  pB2 + kk);
    };

    const int nIt = D_IN / 32;  // 64
    uint32_t ldOff = 0;
#pragma unroll
    for (int s = 0; s < NS - 1; s++) {
        load_stage(ldOff, s * 32); cp_commit();
        ldOff += STAGE;
    }

    uint32_t cmOff = 0;
    int kNext = (NS - 1) * 32;
    for (int i = 0; i < nIt; i++) {
        CP_WAIT(NS - 2);
        __syncthreads();
        if (kNext < D_IN) {
            load_stage(ldOff, kNext);
            ldOff += STAGE; if (ldOff == NS * STAGE) ldOff = 0;
            kNext += 32;
        }
        cp_commit();
        mma_step(cx, cmOff, acc);
        cmOff += STAGE; if (cmOff == NS * STAGE) cmOff = 0;
    }

    // epilogue: bias + gelu -> fp16 h
    const int mrow0 = rowBase + cx.wm * 32 + (cx.lane >> 2);
#pragma unroll
    for (int mt = 0; mt < 2; mt++) {
#pragma unroll
        for (int j = 0; j < 8; j++) {
            const int nl = cx.wn * 64 + j * 8 + (cx.lane & 3) * 2;
            const float b0 = bs[nl], b1 = bs[nl + 1];
            const float* c = acc[mt][j];
#pragma unroll
            for (int hrow = 0; hrow < 2; hrow++) {
                const float v0 = gelu_exact(c[2 * hrow]     + b0);
                const float v1 = gelu_exact(c[2 * hrow + 1] + b1);
                const uint32_t hp = (uint32_t)__half_as_ushort(__float2half(v0)) |
                                    ((uint32_t)__half_as_ushort(__float2half(v1)) << 16);
                const size_t idx = (size_t)(mrow0 + mt * 16 + hrow * 8) * D_HID + colBase + nl;
                *(uint32_t*)(g_h + idx) = hp;
            }
        }
    }
}

// ===========================================================================
// GEMM2: out = (h @ w_down^T) * scale + b_down
// ===========================================================================
__global__ __launch_bounds__(NTHREADS, 1)
void ffn_g2_mma(const float* __restrict__ scale, const float* __restrict__ bias,
                float* __restrict__ out) {
    extern __shared__ char smem[];
    MmaCtx cx; init_ctx(cx, smem);
    const int tid = threadIdx.x;
    const int rowBase = blockIdx.y * BM;
    const int colBase = blockIdx.x * BN;

    float* ss = (float*)(smem + NS * STAGE);
    float* bs = ss + 256;
    if (tid < 256) { ss[tid] = scale[colBase + tid]; bs[tid] = bias[colBase + tid]; }

    const int lr = tid >> 2, lu = tid & 3;
    const __half* pA  = g_h  + (size_t)(rowBase + lr) * D_HID + lu * 8;
    const __half* pB  = g_wd + (size_t)(colBase + lr) * D_HID + lu * 8;
    const __half* pB2 = pB + (size_t)128 * D_HID;

    float acc[2][8][4];
#pragma unroll
    for (int a = 0; a < 2; a++)
#pragma unroll
        for (int b = 0; b < 8; b++)
#pragma unroll
            for (int c = 0; c < 4; c++) acc[a][b][c] = 0.0f;

    auto load_stage = [&](uint32_t stOff, int kk) {
        const uint32_t d = cx.sb + stOff + cx.dlane;
        cp16(d,          pA + kk);
        cp16(d + 8192,   pB + kk);
        cp16(d + 16384,  pB2 + kk);
    };

    const int nIt = D_HID / 32;  // 256
    uint32_t ldOff = 0;
#pragma unroll
    for (int s = 0; s < NS - 1; s++) {
        load_stage(ldOff, s * 32); cp_commit();
        ldOff += STAGE;
    }

    uint32_t cmOff = 0;
    int kNext = (NS - 1) * 32;
    for (int i = 0; i < nIt; i++) {
        CP_WAIT(NS - 2);
        __syncthreads();
        if (kNext < D_HID) {
            load_stage(ldOff, kNext);
            ldOff += STAGE; if (ldOff == NS * STAGE) ldOff = 0;
            kNext += 32;
        }
        cp_commit();
        mma_step(cx, cmOff, acc);
        cmOff += STAGE; if (cmOff == NS * STAGE) cmOff = 0;
    }

    const int mrow0 = rowBase + cx.wm * 32 + (cx.lane >> 2);
#pragma unroll
    for (int mt = 0; mt < 2; mt++) {
#pragma unroll
        for (int j = 0; j < 8; j++) {
            const int nl = cx.wn * 64 + j * 8 + (cx.lane & 3) * 2;
            const float s0 = ss[nl], s1 = ss[nl + 1];
            const float b0 = bs[nl], b1 = bs[nl + 1];
            const float* c = acc[mt][j];
#pragma unroll
            for (int hrow = 0; hrow < 2; hrow++) {
                const float v0 = fmaf(c[2 * hrow],     s0, b0);
                const float v1 = fmaf(c[2 * hrow + 1], s1, b1);
                float* dst = out + (size_t)(mrow0 + mt * 16 + hrow * 8) * D_IN + colBase + nl;
                *(float2*)dst = make_float2(v0, v1);
            }
        }
    }
}

// ===========================================================================
// conversion kernels
// ===========================================================================
__global__ void cvt_f32_h(const float* __restrict__ in, __half* __restrict__ o, int n4) {
    int i = blockIdx.x * blockDim.x + threadIdx.x;
    if (i >= n4) return;
    float4 v = ((const float4*)in)[i];
    uint32_t p0 = (uint32_t)__half_as_ushort(__float2half(v.x)) |
                  ((uint32_t)__half_as_ushort(__float2half(v.y)) << 16);
    uint32_t p1 = (uint32_t)__half_as_ushort(__float2half(v.z)) |
                  ((uint32_t)__half_as_ushort(__float2half(v.w)) << 16);
    ((uint2*)o)[i] = make_uint2(p0, p1);
}

__global__ void cvt_i32_h(const int* __restrict__ q, __half* __restrict__ o, int n4) {
    int i = blockIdx.x * blockDim.x + threadIdx.x;
    if (i >= n4) return;
    int4 v = ((const int4*)q)[i];
    uint32_t p0 = (uint32_t)__half_as_ushort(__float2half((float)v.x)) |
                  ((uint32_t)__half_as_ushort(__float2half((float)v.y)) << 16);
    uint32_t p1 = (uint32_t)__half_as_ushort(__float2half((float)v.z)) |
                  ((uint32_t)__half_as_ushort(__float2half((float)v.w)) << 16);
    ((uint2*)o)[i] = make_uint2(p0, p1);
}

// ===========================================================================
// launch
// ===========================================================================
extern "C" void kernel_launch(void* const* d_in, const int* in_sizes, int n_in,
                              void* d_out, int out_size) {
    const float* x        = (const float*)d_in[0];
    const float* w_up     = (const float*)d_in[1];
    const float* b_up     = (const float*)d_in[2];
    const int*   w_down_q = (const int*)  d_in[3];
    const float* w_scale  = (const float*)d_in[4];
    const float* b_down   = (const float*)d_in[5];
    float*       out      = (float*)d_out;
    (void)in_sizes; (void)n_in; (void)out_size;

    static bool attr_set = false;
    if (!attr_set) {
        cudaFuncSetAttribute(ffn_g1_mma, cudaFuncAttributeMaxDynamicSharedMemorySize, SMEM_TOT);
        cudaFuncSetAttribute(ffn_g2_mma, cudaFuncAttributeMaxDynamicSharedMemorySize, SMEM_TOT);
        attr_set = true;
    }

    __half *x16, *wu, *wd;
    cudaGetSymbolAddress((void**)&x16, g_x16);
    cudaGetSymbolAddress((void**)&wu, g_wu);
    cudaGetSymbolAddress((void**)&wd, g_wd);

    {
        int n4 = (M_TOK * D_IN) / 4;
        cvt_f32_h<<<(n4 + 255) / 256, 256>>>(x, x16, n4);
    }
    {
        int n4 = (D_HID * D_IN) / 4;
        cvt_f32_h<<<(n4 + 255) / 256, 256>>>(w_up, wu, n4);
    }
    {
        int n4 = (D_IN * D_HID) / 4;
        cvt_i32_h<<<(n4 + 255) / 256, 256>>>(w_down_q, wd, n4);
    }

    dim3 block(NTHREADS);
    dim3 grid1(D_HID / BN, M_TOK / BM);  // 32 x 128
    dim3 grid2(D_IN / BN,  M_TOK / BM);  // 8 x 128

    ffn_g1_mma<<<grid1, block, SMEM_TOT>>>(b_up);
    ffn_g2_mma<<<grid2, block, SMEM_TOT>>>(w_scale, b_down, out);
}